// round 11
// baseline (speedup 1.0000x reference)
#include <cuda_runtime.h>
#include <cstdint>
#include <cstddef>

// ===================== edge kernel (mma.sync tf32) =========================
#define THREADS_E 512
#define TILE_E    128
#define EK        268
#define KPAD      272
#define NKS       34            // total k-steps (K=8 each)
#define KS0       18            // chunk0 k-steps  (k 0..143)
#define KS1       16            // chunk1 k-steps  (k 144..271)
#define DC        128
#define MPAD      136           // A buffer row stride (mod 32 == 8)
#define SSTRIDE   132           // staging row stride

// smem layout (bytes)
#define BPACK_FLTS (NKS * 16 * 32 * 2)         // 34816 floats = 139264 B
#define ABUF_FLTS  (KS0 * 8 * MPAD)            // 19584 floats = 78336 B
#define BPACK_OFF  0
#define ABUF_OFF   (BPACK_FLTS * 4)
#define PAR_OFF    (ABUF_OFF + ABUF_FLTS * 4)
#define SMEM_E     (PAR_OFF + 3 * 128 * 4)     // 219136 B total

// RBF recurrence constants: db = (20/16? no) = DMU*0.8 = (20/15)*0.8 = 16/15
//   db^2 = 256/225 = 1.13777778;  k0 = exp(-db^2);  c2 = exp(-2*db^2)
#define DB2   1.13777778f
#define TWODB 2.13333333f       // 2*db

__device__ __forceinline__ uint32_t to_tf32(float f) {
    uint32_t r;
    asm("cvt.rna.tf32.f32 %0, %1;" : "=r"(r) : "f"(f));
    return r;
}

__device__ __forceinline__ void mma_tf32(float& d0, float& d1, float& d2, float& d3,
                                         uint32_t a0, uint32_t a1, uint32_t a2, uint32_t a3,
                                         uint32_t b0, uint32_t b1) {
    asm volatile("mma.sync.aligned.m16n8k8.row.col.f32.tf32.tf32.f32 "
                 "{%0,%1,%2,%3},{%4,%5,%6,%7},{%8,%9},{%0,%1,%2,%3};"
                 : "+f"(d0), "+f"(d1), "+f"(d2), "+f"(d3)
                 : "r"(a0), "r"(a1), "r"(a2), "r"(a3), "r"(b0), "r"(b1));
}

__device__ __forceinline__ void norm3g(float& x, float& y, float& z) {
    float n = sqrtf(x*x + y*y + z*z);
    n = (n == 0.0f) ? 1.0f : n;
    float inv = 1.0f / n;
    x *= inv; y *= inv; z *= inv;
}

// compile-time pair index -> S/Dv stay in registers
template<int P, int KB>
__device__ __forceinline__ void rbf_pair(const float* __restrict__ S,
                                         const float* __restrict__ Dv,
                                         uint32_t* __restrict__ Au,
                                         int eP, float k0, float c2)
{
    constexpr int EPa[16] = {1,1,2,1,0,1,3,2,2,0,2,3,0,0,3,3};
    constexpr int EPb[16] = {1,2,1,0,1,3,1,2,0,2,3,2,0,3,0,3};
    const float* sa = S  + EPa[P] * 3;
    const float* db = Dv + EPb[P] * 3;
    float dx = sa[0]-db[0], dy = sa[1]-db[1], dz = sa[2]-db[2];
    float Dd = sqrtf(dx*dx + dy*dy + dz*dz + 1e-6f);
    uint32_t* row = Au + (P * 16 - KB) * MPAD + eP;
    float av = Dd * 0.8f;
    float E0 = __expf(-av * av);
    if (E0 > 0.0f) {
        float rk = __expf(TWODB * av) * k0;
        float v = E0;
        row[0] = to_tf32(v);
        #pragma unroll
        for (int i = 1; i < 16; i++) {
            v *= rk; rk *= c2;
            row[i * MPAD] = to_tf32(v);
        }
    } else {   // D > ~11.7: direct eval (essentially never taken)
        #pragma unroll
        for (int i = 0; i < 16; i++) {
            float t = (Dd - (float)i * (20.0f/15.0f)) * 0.8f;
            row[i * MPAD] = to_tf32(__expf(-t * t));
        }
    }
}

__global__ void __launch_bounds__(THREADS_E, 1)
edge_kernel_mma(const float* __restrict__ X,
                const int* __restrict__ idxA, const int* __restrict__ idxB,
                const float* __restrict__ Wg, const float* __restrict__ bg,
                const float* __restrict__ gg, const float* __restrict__ betag,
                float* __restrict__ outA, float* __restrict__ outB,
                int E, int N)
{
    constexpr int ORD[4] = {1,0,2,3};

    extern __shared__ char smem[];
    uint32_t* Bp  = (uint32_t*)(smem + BPACK_OFF);   // packed tf32 weights
    uint32_t* Au  = (uint32_t*)(smem + ABUF_OFF);    // tf32 feature buffer
    float*    stg = (float*)(smem + ABUF_OFF);       // staging (reuses Au)
    float*    sB  = (float*)(smem + PAR_OFF);
    float*    sG  = sB + 128;
    float*    sBe = sG + 128;

    const int tid  = threadIdx.x;
    const int lane = tid & 31;
    const int wid  = tid >> 5;

    const float k0 = __expf(-DB2);
    const float c2 = __expf(-2.0f * DB2);

    // ---- init: pack weights (tf32, fragment-ordered), params ----
    for (int i = tid; i < NKS * 16 * 32; i += THREADS_E) {
        const int l  = i & 31;
        const int nt = (i >> 5) & 15;
        const int ks = i >> 9;
        const int n  = nt * 8 + (l >> 2);
        const int k0i = ks * 8 + (l & 3);
        const int k1i = k0i + 4;
        float w0 = (k0i < EK) ? Wg[n * EK + k0i] : 0.0f;
        float w1 = (k1i < EK) ? Wg[n * EK + k1i] : 0.0f;
        Bp[i * 2 + 0] = to_tf32(w0);
        Bp[i * 2 + 1] = to_tf32(w1);
    }
    if (tid < 128) { sB[tid] = bg[tid]; sG[tid] = gg[tid]; sBe[tid] = betag[tid]; }
    __syncthreads();

    // GEMM role: warp grid 4 (M) x 4 (N)
    const int wm = wid >> 2;          // 0..3 -> m band of 32
    const int wn = wid & 3;           // 0..3 -> n band of 32
    const int m0 = wm * 32;
    const uint32_t* Ath = Au + (lane & 3) * MPAD + (lane >> 2);

    const int tilesPer = (E + TILE_E - 1) / TILE_E;
    const int totTiles = 2 * tilesPer;

    const int eP = tid & 127;         // producer edge
    const int qP = tid >> 7;          // producer quarter (0..3)

    for (int tile = blockIdx.x; tile < totTiles; tile += gridDim.x) {
        const int which = (tile >= tilesPer);
        const int* idx  = which ? idxB : idxA;
        float* outp     = which ? outB : outA;
        const int base  = (which ? (tile - tilesPer) : tile) * TILE_E;

        float acc[2][4][4];
        #pragma unroll
        for (int i = 0; i < 2; i++)
            #pragma unroll
            for (int j = 0; j < 4; j++)
                #pragma unroll
                for (int c = 0; c < 4; c++) acc[i][j][c] = 0.0f;

        // ================= two K-chunks =================
        #pragma unroll
        for (int ch = 0; ch < 2; ch++) {
            // ---- produce features for this chunk ----
            {
                const int egl = base + eP;
                const int e   = (egl < E) ? egl : (E - 1);
                const int src = idx[e];
                const int dst = idx[E + e];
                const float4* Sp4 = (const float4*)(X + (size_t)src * 12);
                const float4* Dp4 = (const float4*)(X + (size_t)dst * 12);
                float4 s0 = Sp4[0], s1 = Sp4[1], s2 = Sp4[2];
                float4 dd0 = Dp4[0], dd1 = Dp4[1], dd2 = Dp4[2];
                float S[12]  = {s0.x,s0.y,s0.z,s0.w,s1.x,s1.y,s1.z,s1.w,s2.x,s2.y,s2.z,s2.w};
                float Dv[12] = {dd0.x,dd0.y,dd0.z,dd0.w,dd1.x,dd1.y,dd1.z,dd1.w,dd2.x,dd2.y,dd2.z,dd2.w};

                if (ch == 0) {
                    if (qP == 0) {
                        rbf_pair<0,0>(S,Dv,Au,eP,k0,c2);
                        rbf_pair<1,0>(S,Dv,Au,eP,k0,c2);
                        rbf_pair<2,0>(S,Dv,Au,eP,k0,c2);
                    } else if (qP == 1) {
                        rbf_pair<3,0>(S,Dv,Au,eP,k0,c2);
                        rbf_pair<4,0>(S,Dv,Au,eP,k0,c2);
                    } else if (qP == 2) {
                        rbf_pair<5,0>(S,Dv,Au,eP,k0,c2);
                        rbf_pair<6,0>(S,Dv,Au,eP,k0,c2);
                    } else {
                        rbf_pair<7,0>(S,Dv,Au,eP,k0,c2);
                        rbf_pair<8,0>(S,Dv,Au,eP,k0,c2);
                    }
                } else {
                    if (qP == 0) {
                        rbf_pair<9,144>(S,Dv,Au,eP,k0,c2);
                        rbf_pair<10,144>(S,Dv,Au,eP,k0,c2);
                    } else if (qP == 1) {
                        rbf_pair<11,144>(S,Dv,Au,eP,k0,c2);
                        rbf_pair<12,144>(S,Dv,Au,eP,k0,c2);
                    } else if (qP == 2) {
                        rbf_pair<13,144>(S,Dv,Au,eP,k0,c2);
                        rbf_pair<14,144>(S,Dv,Au,eP,k0,c2);
                        rbf_pair<15,144>(S,Dv,Au,eP,k0,c2);
                    } else {
                        // directions -> buffer rows 112..123
                        float q0x=0.f,q0y=0.f,q0z=0.f,q1x=0.f,q1y=0.f,q1z=0.f,
                              q2x=0.f,q2y=0.f,q2z=0.f;
                        if (src != N - 1) {
                            float u0x=S[3]-S[0], u0y=S[4]-S[1], u0z=S[5]-S[2];
                            norm3g(u0x,u0y,u0z);
                            float u1x=S[6]-S[3], u1y=S[7]-S[4], u1z=S[8]-S[5];
                            norm3g(u1x,u1y,u1z);
                            float nx=u0y*u1z-u0z*u1y, ny=u0z*u1x-u0x*u1z, nz=u0x*u1y-u0y*u1x;
                            norm3g(nx,ny,nz);
                            float bx=u0x-u1x, by=u0y-u1y, bz=u0z-u1z;
                            norm3g(bx,by,bz);
                            float cx=by*nz-bz*ny, cy=bz*nx-bx*nz, cz=bx*ny-by*nx;
                            q0x=bx;q0y=by;q0z=bz; q1x=nx;q1y=ny;q1z=nz; q2x=cx;q2y=cy;q2z=cz;
                        }
                        uint32_t* dbase = Au + 112 * MPAD + eP;
                        #pragma unroll
                        for (int a = 0; a < 4; a++) {
                            const float* da = Dv + ORD[a] * 3;
                            float xx=da[0]-S[0], xy=da[1]-S[1], xz=da[2]-S[2];
                            float vx=q0x*xx+q1x*xy+q2x*xz;
                            float vy=q0y*xx+q1y*xy+q2y*xz;
                            float vz=q0z*xx+q1z*xy+q2z*xz;
                            norm3g(vx,vy,vz);
                            dbase[(a*3+0)*MPAD] = to_tf32(vx);
                            dbase[(a*3+1)*MPAD] = to_tf32(vy);
                            dbase[(a*3+2)*MPAD] = to_tf32(vz);
                        }
                        // zero pad rows 124..127
                        for (int i = eP; i < 4 * MPAD; i += 128)
                            Au[124 * MPAD + i] = 0u;
                    }
                }
            }
            __syncthreads();

            // ---- GEMM over this chunk ----
            const int nks = ch ? KS1 : KS0;
            const uint32_t* Bth = Bp + ((ch ? (KS0*16) : 0) + wn * 4) * 64 + lane * 2;
            #pragma unroll 2
            for (int ksl = 0; ksl < nks; ksl++) {
                const uint32_t* ap = Ath + ksl * (8 * MPAD) + m0;
                uint32_t a[2][4];
                #pragma unroll
                for (int i = 0; i < 2; i++) {
                    const uint32_t* q = ap + i * 16;
                    a[i][0] = q[0];
                    a[i][1] = q[8];
                    a[i][2] = q[4 * MPAD];
                    a[i][3] = q[4 * MPAD + 8];
                }
                const uint32_t* bp = Bth + ksl * (16 * 64);
                #pragma unroll
                for (int j = 0; j < 4; j++) {
                    uint2 b = *(const uint2*)(bp + j * 64);
                    mma_tf32(acc[0][j][0], acc[0][j][1], acc[0][j][2], acc[0][j][3],
                             a[0][0], a[0][1], a[0][2], a[0][3], b.x, b.y);
                    mma_tf32(acc[1][j][0], acc[1][j][1], acc[1][j][2], acc[1][j][3],
                             a[1][0], a[1][1], a[1][2], a[1][3], b.x, b.y);
                }
            }
            __syncthreads();   // chunk done; producers may overwrite Au
        }

        // ================= epilogue =================
        // stage C fragments into stg (reuses Au memory)
        {
            #pragma unroll
            for (int i = 0; i < 2; i++) {
                const int m = wm * 32 + i * 16 + (lane >> 2);
                #pragma unroll
                for (int j = 0; j < 4; j++) {
                    const int n = wn * 32 + j * 8 + (lane & 3) * 2;
                    *(float2*)(stg + m * SSTRIDE + n)       =
                        make_float2(acc[i][j][0], acc[i][j][1]);
                    *(float2*)(stg + (m + 8) * SSTRIDE + n) =
                        make_float2(acc[i][j][2], acc[i][j][3]);
                }
            }
        }
        __syncthreads();

        // LN: 4 threads per edge, channels interleaved by 4s
        {
            const int er   = tid >> 2;
            const int part = tid & 3;
            float* row = stg + er * SSTRIDE;
            float v[32];
            float sum = 0.0f;
            #pragma unroll
            for (int k = 0; k < 8; k++) {
                const int c = part * 4 + k * 16;
                float4 x = *(const float4*)(row + c);
                v[k*4+0] = x.x + sB[c+0];
                v[k*4+1] = x.y + sB[c+1];
                v[k*4+2] = x.z + sB[c+2];
                v[k*4+3] = x.w + sB[c+3];
                sum += v[k*4+0] + v[k*4+1] + v[k*4+2] + v[k*4+3];
            }
            sum += __shfl_xor_sync(0xffffffffu, sum, 1);
            sum += __shfl_xor_sync(0xffffffffu, sum, 2);
            float mu = sum * (1.0f / 128.0f);
            float sq = 0.0f;
            #pragma unroll
            for (int c = 0; c < 32; c++) {
                float d = v[c] - mu;
                v[c] = d;
                sq += d * d;
            }
            sq += __shfl_xor_sync(0xffffffffu, sq, 1);
            sq += __shfl_xor_sync(0xffffffffu, sq, 2);
            float inv = 1.0f / (sqrtf(sq * (1.0f / 127.0f) + 1e-6f) + 1e-6f);
            #pragma unroll
            for (int k = 0; k < 8; k++) {
                const int c = part * 4 + k * 16;
                float4 o;
                o.x = sG[c+0] * v[k*4+0] * inv + sBe[c+0];
                o.y = sG[c+1] * v[k*4+1] * inv + sBe[c+1];
                o.z = sG[c+2] * v[k*4+2] * inv + sBe[c+2];
                o.w = sG[c+3] * v[k*4+3] * inv + sBe[c+3];
                *(float4*)(row + c) = o;
            }
        }
        __syncthreads();

        // coalesced store (512 threads)
        {
            const int c0 = (tid & 31) * 4;
            const int r0 = tid >> 5;          // 0..15
            #pragma unroll
            for (int i = 0; i < 8; i++) {
                const int r = r0 + i * 16;
                const int eo = base + r;
                if (eo < E) {
                    float4 x = *(const float4*)(stg + r * SSTRIDE + c0);
                    *(float4*)(outp + (size_t)eo * DC + c0) = x;
                }
            }
        }
        __syncthreads();   // protect stg/Au before next tile
    }
}

// ===================== node kernel (fp32 f32x2) ============================
#define THREADS_N 256
#define TILE_N 64
#define FSN 68
#define NK 96

__device__ __forceinline__ unsigned long long pack2(float a) {
    unsigned long long r;
    unsigned int ai = __float_as_uint(a);
    asm("mov.b64 %0, {%1, %1};" : "=l"(r) : "r"(ai));
    return r;
}
__device__ __forceinline__ void fma2(unsigned long long& d,
                                     unsigned long long a,
                                     unsigned long long b) {
    asm("fma.rn.f32x2 %0, %1, %2, %0;" : "+l"(d) : "l"(a), "l"(b));
}

__global__ void __launch_bounds__(THREADS_N, 1)
node_kernel(const float* __restrict__ X,
            const float* __restrict__ Wg, const float* __restrict__ bg,
            const float* __restrict__ gg, const float* __restrict__ betag,
            float* __restrict__ out, int N)
{
    constexpr int NPa[6] = {1,1,1,0,0,3};
    constexpr int NPb[6] = {0,2,3,2,3,2};
    extern __shared__ float sm[];
    float* Wsm = sm;
    float* F   = Wsm + NK * DC;
    float* sB  = F + NK * FSN;
    float* sG  = sB + DC;
    float* sBe = sG + DC;

    const int tid = threadIdx.x;
    const float k0 = __expf(-DB2);
    const float c2 = __expf(-2.0f * DB2);

    for (int i = tid; i < NK * DC; i += THREADS_N) {
        int k = i >> 7, c = i & 127;
        Wsm[i] = Wg[c * NK + k];
    }
    if (tid < DC) { sB[tid] = bg[tid]; sG[tid] = gg[tid]; sBe[tid] = betag[tid]; }
    __syncthreads();

    const int j    = tid & 3;
    const int eloc = tid >> 2;
    const int cidx = tid & 31;
    const int eg   = tid >> 5;
    const int eBase = eg * 8;
    const int c0   = cidx * 4;
    const int base = blockIdx.x * TILE_N;

    {
        const int n = base + eloc;
        if (n < N) {
            const float* Sx = X + (size_t)n * 12;
            #pragma unroll
            for (int pp = 0; pp < 2; pp++) {
                const int p = j + pp * 4;
                if (p < 6) {
                    const float* sa = Sx + NPa[p] * 3;
                    const float* sb = Sx + NPb[p] * 3;
                    float dx = sa[0]-sb[0], dy = sa[1]-sb[1], dz = sa[2]-sb[2];
                    float Dd = sqrtf(dx*dx + dy*dy + dz*dz + 1e-6f);
                    float* frow = F + (p * 16) * FSN + eloc;
                    float av = Dd * 0.8f;
                    float E0 = __expf(-av * av);
                    if (E0 > 0.0f) {
                        float rk = __expf(TWODB * av) * k0;
                        float v = E0;
                        frow[0] = v;
                        #pragma unroll
                        for (int i = 1; i < 16; i++) {
                            v *= rk; rk *= c2;
                            frow[i * FSN] = v;
                        }
                    } else {
                        #pragma unroll
                        for (int i = 0; i < 16; i++) {
                            float t = (Dd - (float)i * (20.0f/15.0f)) * 0.8f;
                            frow[i * FSN] = __expf(-t * t);
                        }
                    }
                }
            }
        }
    }
    __syncthreads();

    unsigned long long acc[4][4];
    #pragma unroll
    for (int q = 0; q < 4; q++)
        #pragma unroll
        for (int cc = 0; cc < 4; cc++) acc[q][cc] = 0ull;

    #pragma unroll 4
    for (int k = 0; k < NK; k++) {
        const ulonglong2* fp = (const ulonglong2*)(F + k * FSN + eBase);
        ulonglong2 fa = fp[0];
        ulonglong2 fb = fp[1];
        const float4 w = *(const float4*)(Wsm + k * DC + c0);
        unsigned long long w0 = pack2(w.x), w1 = pack2(w.y);
        unsigned long long w2 = pack2(w.z), w3 = pack2(w.w);
        unsigned long long f2[4] = {fa.x, fa.y, fb.x, fb.y};
        #pragma unroll
        for (int q = 0; q < 4; q++) {
            fma2(acc[q][0], f2[q], w0);
            fma2(acc[q][1], f2[q], w1);
            fma2(acc[q][2], f2[q], w2);
            fma2(acc[q][3], f2[q], w3);
        }
    }

    float v[8][4];
    #pragma unroll
    for (int q = 0; q < 4; q++)
        #pragma unroll
        for (int cc = 0; cc < 4; cc++) {
            union { unsigned long long u; float2 f; } cv;
            cv.u = acc[q][cc];
            v[2*q][cc]   = cv.f.x;
            v[2*q+1][cc] = cv.f.y;
        }
    const float b0=sB[c0], b1=sB[c0+1], b2=sB[c0+2], b3=sB[c0+3];
    const float g0=sG[c0], g1=sG[c0+1], g2=sG[c0+2], g3=sG[c0+3];
    const float t0=sBe[c0],t1=sBe[c0+1],t2=sBe[c0+2],t3=sBe[c0+3];

    #pragma unroll
    for (int s = 0; s < 8; s++) {
        float x0=v[s][0]+b0, x1=v[s][1]+b1, x2=v[s][2]+b2, x3=v[s][3]+b3;
        float sum = x0+x1+x2+x3;
        #pragma unroll
        for (int m = 16; m > 0; m >>= 1) sum += __shfl_xor_sync(0xffffffffu, sum, m);
        float mu = sum * (1.0f/128.0f);
        float d0=x0-mu, d1=x1-mu, d2=x2-mu, d3=x3-mu;
        float sq = d0*d0+d1*d1+d2*d2+d3*d3;
        #pragma unroll
        for (int m = 16; m > 0; m >>= 1) sq += __shfl_xor_sync(0xffffffffu, sq, m);
        float inv = 1.0f / (sqrtf(sq * (1.0f/127.0f) + 1e-6f) + 1e-6f);
        const int n2 = base + eBase + s;
        if (n2 < N) {
            float4 o;
            o.x = g0*d0*inv + t0;
            o.y = g1*d1*inv + t1;
            o.z = g2*d2*inv + t2;
            o.w = g3*d3*inv + t3;
            *(float4*)(out + (size_t)n2 * DC + c0) = o;
        }
    }
}

// ===================== launch =====================
extern "C" void kernel_launch(void* const* d_in, const int* in_sizes, int n_in,
                              void* d_out, int out_size)
{
    const float* X   = (const float*)d_in[0];
    const int*   Ein = (const int*)d_in[1];
    const int*   Eex = (const int*)d_in[2];
    const float* nW  = (const float*)d_in[3];
    const float* nb  = (const float*)d_in[4];
    const float* eW  = (const float*)d_in[5];
    const float* eb  = (const float*)d_in[6];
    const float* gn  = (const float*)d_in[7];
    const float* bn  = (const float*)d_in[8];
    const float* ge  = (const float*)d_in[9];
    const float* be  = (const float*)d_in[10];

    const int N = in_sizes[0] / 12;
    const int E = in_sizes[1] / 2;

    float* out   = (float*)d_out;
    float* outV  = out;
    float* outIn = out + (size_t)N * DC;
    float* outEx = outIn + (size_t)E * DC;

    const size_t smN = (size_t)(NK * DC + NK * FSN + 3 * DC) * sizeof(float);
    cudaFuncSetAttribute(edge_kernel_mma,
                         cudaFuncAttributeMaxDynamicSharedMemorySize, SMEM_E);
    cudaFuncSetAttribute(node_kernel,
                         cudaFuncAttributeMaxDynamicSharedMemorySize, (int)smN);

    int sms = 148;
    cudaDeviceGetAttribute(&sms, cudaDevAttrMultiProcessorCount, 0);

    const int nTiles = (N + TILE_N - 1) / TILE_N;
    node_kernel<<<nTiles, THREADS_N, smN>>>(X, nW, nb, gn, bn, outV, N);
    edge_kernel_mma<<<sms, THREADS_E, SMEM_E>>>(X, Ein, Eex, eW, eb, ge, be,
                                                outIn, outEx, E, N);
}

// round 14
// speedup vs baseline: 1.0200x; 1.0200x over previous
#include <cuda_runtime.h>
#include <cstdint>
#include <cstddef>

// ===================== edge kernel (mma.sync tf32) =========================
#define THREADS_E 256
#define TILE_E    128
#define EK        268
#define KPAD      272
#define NKS       34            // total k-steps (K=8 each)
#define KS0       18            // chunk0 k-steps  (k 0..143)
#define KS1       16            // chunk1 k-steps  (k 144..271)
#define DC        128
#define MPAD      136           // A buffer row stride (mod 32 == 8)
#define SSTRIDE   132           // staging row stride

// smem layout (bytes)
#define BPACK_FLTS (NKS * 16 * 32 * 2)         // 34816 floats = 139264 B
#define ABUF_FLTS  (KS0 * 8 * MPAD)            // 19584 floats = 78336 B
#define BPACK_OFF  0
#define ABUF_OFF   (BPACK_FLTS * 4)
#define PAR_OFF    (ABUF_OFF + ABUF_FLTS * 4)
#define SMEM_E     (PAR_OFF + 3 * 128 * 4)     // 219136 B total

// RBF recurrence: db = DMU*0.8 = 16/15; db^2 = 1.13777778
#define DB2   1.13777778f
#define TWODB 2.13333333f       // 2*db

__device__ __forceinline__ uint32_t to_tf32(float f) {
    uint32_t r;
    asm("cvt.rna.tf32.f32 %0, %1;" : "=r"(r) : "f"(f));
    return r;
}

__device__ __forceinline__ void mma_tf32(float& d0, float& d1, float& d2, float& d3,
                                         uint32_t a0, uint32_t a1, uint32_t a2, uint32_t a3,
                                         uint32_t b0, uint32_t b1) {
    asm volatile("mma.sync.aligned.m16n8k8.row.col.f32.tf32.tf32.f32 "
                 "{%0,%1,%2,%3},{%4,%5,%6,%7},{%8,%9},{%0,%1,%2,%3};"
                 : "+f"(d0), "+f"(d1), "+f"(d2), "+f"(d3)
                 : "r"(a0), "r"(a1), "r"(a2), "r"(a3), "r"(b0), "r"(b1));
}

__device__ __forceinline__ void norm3g(float& x, float& y, float& z) {
    float n = sqrtf(x*x + y*y + z*z);
    n = (n == 0.0f) ? 1.0f : n;
    float inv = 1.0f / n;
    x *= inv; y *= inv; z *= inv;
}

// compile-time pair index -> S/Dv stay in registers (no local memory)
template<int P, int KB>
__device__ __forceinline__ void rbf_pair(const float* __restrict__ S,
                                         const float* __restrict__ Dv,
                                         uint32_t* __restrict__ Au,
                                         int eP, float k0, float c2)
{
    constexpr int EPa[16] = {1,1,2,1,0,1,3,2,2,0,2,3,0,0,3,3};
    constexpr int EPb[16] = {1,2,1,0,1,3,1,2,0,2,3,2,0,3,0,3};
    const float* sa = S  + EPa[P] * 3;
    const float* db = Dv + EPb[P] * 3;
    float dx = sa[0]-db[0], dy = sa[1]-db[1], dz = sa[2]-db[2];
    float Dd = sqrtf(dx*dx + dy*dy + dz*dz + 1e-6f);
    uint32_t* row = Au + (P * 16 - KB) * MPAD + eP;
    float av = Dd * 0.8f;
    float E0 = __expf(-av * av);
    if (E0 > 0.0f) {
        float rk = __expf(TWODB * av) * k0;
        float v = E0;
        row[0] = to_tf32(v);
        #pragma unroll
        for (int i = 1; i < 16; i++) {
            v *= rk; rk *= c2;
            row[i * MPAD] = to_tf32(v);
        }
    } else {   // D > ~11.7: direct eval (essentially never taken)
        #pragma unroll
        for (int i = 0; i < 16; i++) {
            float t = (Dd - (float)i * (20.0f/15.0f)) * 0.8f;
            row[i * MPAD] = to_tf32(__expf(-t * t));
        }
    }
}

// GEMM fragment loaders
__device__ __forceinline__ void load_afrag(const uint32_t* __restrict__ ap,
                                           uint32_t a[2][4]) {
    #pragma unroll
    for (int i = 0; i < 2; i++) {
        const uint32_t* q = ap + i * 16;
        a[i][0] = q[0];
        a[i][1] = q[8];
        a[i][2] = q[4 * MPAD];
        a[i][3] = q[4 * MPAD + 8];
    }
}
__device__ __forceinline__ void load_bfrag(const uint32_t* __restrict__ bp,
                                           uint2 b[8]) {
    #pragma unroll
    for (int j = 0; j < 8; j++)
        b[j] = *(const uint2*)(bp + j * 64);
}
__device__ __forceinline__ void do_mmas(float acc[2][8][4],
                                        const uint32_t a[2][4],
                                        const uint2 b[8]) {
    #pragma unroll
    for (int j = 0; j < 8; j++) {
        mma_tf32(acc[0][j][0], acc[0][j][1], acc[0][j][2], acc[0][j][3],
                 a[0][0], a[0][1], a[0][2], a[0][3], b[j].x, b[j].y);
        mma_tf32(acc[1][j][0], acc[1][j][1], acc[1][j][2], acc[1][j][3],
                 a[1][0], a[1][1], a[1][2], a[1][3], b[j].x, b[j].y);
    }
}

__global__ void __launch_bounds__(THREADS_E, 1)
edge_kernel_mma(const float* __restrict__ X,
                const int* __restrict__ idxA, const int* __restrict__ idxB,
                const float* __restrict__ Wg, const float* __restrict__ bg,
                const float* __restrict__ gg, const float* __restrict__ betag,
                float* __restrict__ outA, float* __restrict__ outB,
                int E, int N)
{
    constexpr int ORD[4] = {1,0,2,3};

    extern __shared__ char smem[];
    uint32_t* Bp  = (uint32_t*)(smem + BPACK_OFF);   // packed tf32 weights
    uint32_t* Au  = (uint32_t*)(smem + ABUF_OFF);    // tf32 feature buffer
    float*    stg = (float*)(smem + ABUF_OFF);       // staging (reuses Au)
    float*    sB  = (float*)(smem + PAR_OFF);
    float*    sG  = sB + 128;
    float*    sBe = sG + 128;

    const int tid  = threadIdx.x;
    const int lane = tid & 31;
    const int wid  = tid >> 5;

    const float k0 = __expf(-DB2);
    const float c2 = __expf(-2.0f * DB2);

    // ---- init: pack weights (tf32, fragment-ordered), params ----
    for (int i = tid; i < NKS * 16 * 32; i += THREADS_E) {
        const int l  = i & 31;
        const int nt = (i >> 5) & 15;
        const int ks = i >> 9;
        const int n  = nt * 8 + (l >> 2);
        const int k0i = ks * 8 + (l & 3);
        const int k1i = k0i + 4;
        float w0 = (k0i < EK) ? Wg[n * EK + k0i] : 0.0f;
        float w1 = (k1i < EK) ? Wg[n * EK + k1i] : 0.0f;
        Bp[i * 2 + 0] = to_tf32(w0);
        Bp[i * 2 + 1] = to_tf32(w1);
    }
    if (tid < 128) { sB[tid] = bg[tid]; sG[tid] = gg[tid]; sBe[tid] = betag[tid]; }
    __syncthreads();

    // GEMM role: warp grid 4 (M) x 2 (N)
    const int wm = wid >> 1;          // 0..3 -> m band of 32
    const int wn = wid & 1;           // 0..1 -> n band of 64
    const uint32_t* Ath = Au + (lane & 3) * MPAD + (lane >> 2) + wm * 32;

    const int tilesPer = (E + TILE_E - 1) / TILE_E;
    const int totTiles = 2 * tilesPer;

    const int eP = tid & 127;         // producer edge
    const int hP = tid >> 7;          // producer half (0/1)

    for (int tile = blockIdx.x; tile < totTiles; tile += gridDim.x) {
        const int which = (tile >= tilesPer);
        const int* idx  = which ? idxB : idxA;
        float* outp     = which ? outB : outA;
        const int base  = (which ? (tile - tilesPer) : tile) * TILE_E;

        // ---- gather X once per tile ----
        const int egl = base + eP;
        const int e   = (egl < E) ? egl : (E - 1);
        const int src = idx[e];
        const int dst = idx[E + e];
        const float4* Sp4 = (const float4*)(X + (size_t)src * 12);
        const float4* Dp4 = (const float4*)(X + (size_t)dst * 12);
        float4 s0 = Sp4[0], s1 = Sp4[1], s2 = Sp4[2];
        float4 dd0 = Dp4[0], dd1 = Dp4[1], dd2 = Dp4[2];
        float S[12]  = {s0.x,s0.y,s0.z,s0.w,s1.x,s1.y,s1.z,s1.w,s2.x,s2.y,s2.z,s2.w};
        float Dv[12] = {dd0.x,dd0.y,dd0.z,dd0.w,dd1.x,dd1.y,dd1.z,dd1.w,dd2.x,dd2.y,dd2.z,dd2.w};

        float acc[2][8][4];
        #pragma unroll
        for (int i = 0; i < 2; i++)
            #pragma unroll
            for (int j = 0; j < 8; j++)
                #pragma unroll
                for (int c = 0; c < 4; c++) acc[i][j][c] = 0.0f;

        // ================= two K-chunks =================
        #pragma unroll
        for (int ch = 0; ch < 2; ch++) {
            // ---- produce features for this chunk (balanced halves) ----
            if (ch == 0) {
                if (hP == 0) {
                    rbf_pair<0,0>(S,Dv,Au,eP,k0,c2);
                    rbf_pair<1,0>(S,Dv,Au,eP,k0,c2);
                    rbf_pair<2,0>(S,Dv,Au,eP,k0,c2);
                    rbf_pair<3,0>(S,Dv,Au,eP,k0,c2);
                    rbf_pair<4,0>(S,Dv,Au,eP,k0,c2);
                } else {
                    rbf_pair<5,0>(S,Dv,Au,eP,k0,c2);
                    rbf_pair<6,0>(S,Dv,Au,eP,k0,c2);
                    rbf_pair<7,0>(S,Dv,Au,eP,k0,c2);
                    rbf_pair<8,0>(S,Dv,Au,eP,k0,c2);
                }
            } else {
                if (hP == 0) {
                    rbf_pair<9,144>(S,Dv,Au,eP,k0,c2);
                    rbf_pair<10,144>(S,Dv,Au,eP,k0,c2);
                    rbf_pair<11,144>(S,Dv,Au,eP,k0,c2);
                    // directions -> buffer rows 112..123
                    float q0x=0.f,q0y=0.f,q0z=0.f,q1x=0.f,q1y=0.f,q1z=0.f,
                          q2x=0.f,q2y=0.f,q2z=0.f;
                    if (src != N - 1) {
                        float u0x=S[3]-S[0], u0y=S[4]-S[1], u0z=S[5]-S[2];
                        norm3g(u0x,u0y,u0z);
                        float u1x=S[6]-S[3], u1y=S[7]-S[4], u1z=S[8]-S[5];
                        norm3g(u1x,u1y,u1z);
                        float nx=u0y*u1z-u0z*u1y, ny=u0z*u1x-u0x*u1z, nz=u0x*u1y-u0y*u1x;
                        norm3g(nx,ny,nz);
                        float bx=u0x-u1x, by=u0y-u1y, bz=u0z-u1z;
                        norm3g(bx,by,bz);
                        float cx=by*nz-bz*ny, cy=bz*nx-bx*nz, cz=bx*ny-by*nx;
                        q0x=bx;q0y=by;q0z=bz; q1x=nx;q1y=ny;q1z=nz; q2x=cx;q2y=cy;q2z=cz;
                    }
                    uint32_t* dbase = Au + 112 * MPAD + eP;
                    #pragma unroll
                    for (int a = 0; a < 4; a++) {
                        const float* da = Dv + ORD[a] * 3;
                        float xx=da[0]-S[0], xy=da[1]-S[1], xz=da[2]-S[2];
                        float vx=q0x*xx+q1x*xy+q2x*xz;
                        float vy=q0y*xx+q1y*xy+q2y*xz;
                        float vz=q0z*xx+q1z*xy+q2z*xz;
                        norm3g(vx,vy,vz);
                        dbase[(a*3+0)*MPAD] = to_tf32(vx);
                        dbase[(a*3+1)*MPAD] = to_tf32(vy);
                        dbase[(a*3+2)*MPAD] = to_tf32(vz);
                    }
                } else {
                    rbf_pair<12,144>(S,Dv,Au,eP,k0,c2);
                    rbf_pair<13,144>(S,Dv,Au,eP,k0,c2);
                    rbf_pair<14,144>(S,Dv,Au,eP,k0,c2);
                    rbf_pair<15,144>(S,Dv,Au,eP,k0,c2);
                    // zero pad rows 124..127
                    for (int i = eP; i < 4 * MPAD; i += 128)
                        Au[124 * MPAD + i] = 0u;
                }
            }
            __syncthreads();

            // ---- GEMM over this chunk (double-buffered fragments) ----
            const int nks = ch ? KS1 : KS0;
            const uint32_t* Bth = Bp + ((ch ? (KS0*16) : 0) + wn * 8) * 64 + lane * 2;

            uint32_t a0[2][4], a1[2][4];
            uint2    b0[8],    b1[8];
            load_afrag(Ath, a0);
            load_bfrag(Bth, b0);
            int ksl = 0;
            for (; ksl + 2 <= nks; ksl += 2) {
                load_afrag(Ath + (ksl+1) * (8 * MPAD), a1);
                load_bfrag(Bth + (ksl+1) * (16 * 64),  b1);
                do_mmas(acc, a0, b0);
                if (ksl + 2 < nks) {
                    load_afrag(Ath + (ksl+2) * (8 * MPAD), a0);
                    load_bfrag(Bth + (ksl+2) * (16 * 64),  b0);
                }
                do_mmas(acc, a1, b1);
            }
            if (ksl < nks) do_mmas(acc, a0, b0);   // odd tail (not taken: 18/16 even)
            __syncthreads();   // chunk done; producers may overwrite Au
        }

        // ================= epilogue =================
        // stage C fragments into stg (reuses Au memory)
        {
            #pragma unroll
            for (int i = 0; i < 2; i++) {
                const int m = wm * 32 + i * 16 + (lane >> 2);
                #pragma unroll
                for (int j = 0; j < 8; j++) {
                    const int n = wn * 64 + j * 8 + (lane & 3) * 2;
                    *(float2*)(stg + m * SSTRIDE + n)       =
                        make_float2(acc[i][j][0], acc[i][j][1]);
                    *(float2*)(stg + (m + 8) * SSTRIDE + n) =
                        make_float2(acc[i][j][2], acc[i][j][3]);
                }
            }
        }
        __syncthreads();

        // LN: 2 threads per edge (64 channels each)
        {
            const int er   = tid >> 1;
            const int half = tid & 1;
            float* row = stg + er * SSTRIDE + half * 64;
            float v[64];
            float sum = 0.0f;
            #pragma unroll
            for (int c = 0; c < 64; c += 4) {
                float4 x = *(const float4*)(row + c);
                v[c+0] = x.x + sB[half*64 + c+0];
                v[c+1] = x.y + sB[half*64 + c+1];
                v[c+2] = x.z + sB[half*64 + c+2];
                v[c+3] = x.w + sB[half*64 + c+3];
                sum += v[c+0] + v[c+1] + v[c+2] + v[c+3];
            }
            sum += __shfl_xor_sync(0xffffffffu, sum, 1);
            float mu = sum * (1.0f / 128.0f);
            float sq = 0.0f;
            #pragma unroll
            for (int c = 0; c < 64; c++) {
                float d = v[c] - mu;
                v[c] = d;
                sq += d * d;
            }
            sq += __shfl_xor_sync(0xffffffffu, sq, 1);
            float inv = 1.0f / (sqrtf(sq * (1.0f / 127.0f) + 1e-6f) + 1e-6f);
            #pragma unroll
            for (int c = 0; c < 64; c += 4) {
                float4 o;
                o.x = sG[half*64 + c+0] * v[c+0] * inv + sBe[half*64 + c+0];
                o.y = sG[half*64 + c+1] * v[c+1] * inv + sBe[half*64 + c+1];
                o.z = sG[half*64 + c+2] * v[c+2] * inv + sBe[half*64 + c+2];
                o.w = sG[half*64 + c+3] * v[c+3] * inv + sBe[half*64 + c+3];
                *(float4*)(row + c) = o;
            }
        }
        __syncthreads();

        // coalesced store
        {
            const int c0 = (tid & 31) * 4;
            const int r0 = tid >> 5;
            #pragma unroll
            for (int i = 0; i < 16; i++) {
                const int r = r0 + i * 8;
                const int eo = base + r;
                if (eo < E) {
                    float4 x = *(const float4*)(stg + r * SSTRIDE + c0);
                    *(float4*)(outp + (size_t)eo * DC + c0) = x;
                }
            }
        }
        __syncthreads();   // protect stg/Au before next tile
    }
}

// ===================== node kernel (fp32 f32x2) ============================
#define THREADS_N 256
#define TILE_N 64
#define FSN 68
#define NK 96

__device__ __forceinline__ unsigned long long pack2(float a) {
    unsigned long long r;
    unsigned int ai = __float_as_uint(a);
    asm("mov.b64 %0, {%1, %1};" : "=l"(r) : "r"(ai));
    return r;
}
__device__ __forceinline__ void fma2(unsigned long long& d,
                                     unsigned long long a,
                                     unsigned long long b) {
    asm("fma.rn.f32x2 %0, %1, %2, %0;" : "+l"(d) : "l"(a), "l"(b));
}

__global__ void __launch_bounds__(THREADS_N, 1)
node_kernel(const float* __restrict__ X,
            const float* __restrict__ Wg, const float* __restrict__ bg,
            const float* __restrict__ gg, const float* __restrict__ betag,
            float* __restrict__ out, int N)
{
    constexpr int NPa[6] = {1,1,1,0,0,3};
    constexpr int NPb[6] = {0,2,3,2,3,2};
    extern __shared__ float sm[];
    float* Wsm = sm;
    float* F   = Wsm + NK * DC;
    float* sB  = F + NK * FSN;
    float* sG  = sB + DC;
    float* sBe = sG + DC;

    const int tid = threadIdx.x;
    const float k0 = __expf(-DB2);
    const float c2 = __expf(-2.0f * DB2);

    for (int i = tid; i < NK * DC; i += THREADS_N) {
        int k = i >> 7, c = i & 127;
        Wsm[i] = Wg[c * NK + k];
    }
    if (tid < DC) { sB[tid] = bg[tid]; sG[tid] = gg[tid]; sBe[tid] = betag[tid]; }
    __syncthreads();

    const int j    = tid & 3;
    const int eloc = tid >> 2;
    const int cidx = tid & 31;
    const int eg   = tid >> 5;
    const int eBase = eg * 8;
    const int c0   = cidx * 4;
    const int base = blockIdx.x * TILE_N;

    {
        const int n = base + eloc;
        if (n < N) {
            const float* Sx = X + (size_t)n * 12;
            #pragma unroll
            for (int pp = 0; pp < 2; pp++) {
                const int p = j + pp * 4;
                if (p < 6) {
                    const float* sa = Sx + NPa[p] * 3;
                    const float* sb = Sx + NPb[p] * 3;
                    float dx = sa[0]-sb[0], dy = sa[1]-sb[1], dz = sa[2]-sb[2];
                    float Dd = sqrtf(dx*dx + dy*dy + dz*dz + 1e-6f);
                    float* frow = F + (p * 16) * FSN + eloc;
                    float av = Dd * 0.8f;
                    float E0 = __expf(-av * av);
                    if (E0 > 0.0f) {
                        float rk = __expf(TWODB * av) * k0;
                        float v = E0;
                        frow[0] = v;
                        #pragma unroll
                        for (int i = 1; i < 16; i++) {
                            v *= rk; rk *= c2;
                            frow[i * FSN] = v;
                        }
                    } else {
                        #pragma unroll
                        for (int i = 0; i < 16; i++) {
                            float t = (Dd - (float)i * (20.0f/15.0f)) * 0.8f;
                            frow[i * FSN] = __expf(-t * t);
                        }
                    }
                }
            }
        }
    }
    __syncthreads();

    unsigned long long acc[4][4];
    #pragma unroll
    for (int q = 0; q < 4; q++)
        #pragma unroll
        for (int cc = 0; cc < 4; cc++) acc[q][cc] = 0ull;

    #pragma unroll 4
    for (int k = 0; k < NK; k++) {
        const ulonglong2* fp = (const ulonglong2*)(F + k * FSN + eBase);
        ulonglong2 fa = fp[0];
        ulonglong2 fb = fp[1];
        const float4 w = *(const float4*)(Wsm + k * DC + c0);
        unsigned long long w0 = pack2(w.x), w1 = pack2(w.y);
        unsigned long long w2 = pack2(w.z), w3 = pack2(w.w);
        unsigned long long f2[4] = {fa.x, fa.y, fb.x, fb.y};
        #pragma unroll
        for (int q = 0; q < 4; q++) {
            fma2(acc[q][0], f2[q], w0);
            fma2(acc[q][1], f2[q], w1);
            fma2(acc[q][2], f2[q], w2);
            fma2(acc[q][3], f2[q], w3);
        }
    }

    float v[8][4];
    #pragma unroll
    for (int q = 0; q < 4; q++)
        #pragma unroll
        for (int cc = 0; cc < 4; cc++) {
            union { unsigned long long u; float2 f; } cv;
            cv.u = acc[q][cc];
            v[2*q][cc]   = cv.f.x;
            v[2*q+1][cc] = cv.f.y;
        }
    const float b0=sB[c0], b1=sB[c0+1], b2=sB[c0+2], b3=sB[c0+3];
    const float g0=sG[c0], g1=sG[c0+1], g2=sG[c0+2], g3=sG[c0+3];
    const float t0=sBe[c0],t1=sBe[c0+1],t2=sBe[c0+2],t3=sBe[c0+3];

    #pragma unroll
    for (int s = 0; s < 8; s++) {
        float x0=v[s][0]+b0, x1=v[s][1]+b1, x2=v[s][2]+b2, x3=v[s][3]+b3;
        float sum = x0+x1+x2+x3;
        #pragma unroll
        for (int m = 16; m > 0; m >>= 1) sum += __shfl_xor_sync(0xffffffffu, sum, m);
        float mu = sum * (1.0f/128.0f);
        float d0=x0-mu, d1=x1-mu, d2=x2-mu, d3=x3-mu;
        float sq = d0*d0+d1*d1+d2*d2+d3*d3;
        #pragma unroll
        for (int m = 16; m > 0; m >>= 1) sq += __shfl_xor_sync(0xffffffffu, sq, m);
        float inv = 1.0f / (sqrtf(sq * (1.0f/127.0f) + 1e-6f) + 1e-6f);
        const int n2 = base + eBase + s;
        if (n2 < N) {
            float4 o;
            o.x = g0*d0*inv + t0;
            o.y = g1*d1*inv + t1;
            o.z = g2*d2*inv + t2;
            o.w = g3*d3*inv + t3;
            *(float4*)(out + (size_t)n2 * DC + c0) = o;
        }
    }
}

// ===================== launch =====================
extern "C" void kernel_launch(void* const* d_in, const int* in_sizes, int n_in,
                              void* d_out, int out_size)
{
    const float* X   = (const float*)d_in[0];
    const int*   Ein = (const int*)d_in[1];
    const int*   Eex = (const int*)d_in[2];
    const float* nW  = (const float*)d_in[3];
    const float* nb  = (const float*)d_in[4];
    const float* eW  = (const float*)d_in[5];
    const float* eb  = (const float*)d_in[6];
    const float* gn  = (const float*)d_in[7];
    const float* bn  = (const float*)d_in[8];
    const float* ge  = (const float*)d_in[9];
    const float* be  = (const float*)d_in[10];

    const int N = in_sizes[0] / 12;
    const int E = in_sizes[1] / 2;

    float* out   = (float*)d_out;
    float* outV  = out;
    float* outIn = out + (size_t)N * DC;
    float* outEx = outIn + (size_t)E * DC;

    const size_t smN = (size_t)(NK * DC + NK * FSN + 3 * DC) * sizeof(float);
    cudaFuncSetAttribute(edge_kernel_mma,
                         cudaFuncAttributeMaxDynamicSharedMemorySize, SMEM_E);
    cudaFuncSetAttribute(node_kernel,
                         cudaFuncAttributeMaxDynamicSharedMemorySize, (int)smN);

    int sms = 148;
    cudaDeviceGetAttribute(&sms, cudaDevAttrMultiProcessorCount, 0);

    const int nTiles = (N + TILE_N - 1) / TILE_N;
    node_kernel<<<nTiles, THREADS_N, smN>>>(X, nW, nb, gn, bn, outV, N);
    edge_kernel_mma<<<sms, THREADS_E, SMEM_E>>>(X, Ein, Eex, eW, eb, ge, be,
                                                outIn, outEx, E, N);
}

// round 15
// speedup vs baseline: 1.7226x; 1.6888x over previous
#include <cuda_runtime.h>
#include <cstdint>
#include <cstddef>

// ============ edge kernel: warp-specialized mma.sync tf32 pipeline =========
#define THREADS_E 384          // 8 consumer warps + 4 producer warps
#define TILE_E    128
#define EK        268
#define NKS       34           // total K=8 steps (KPAD=272)
#define DC        128
#define MPAD      136          // A buffer row stride (mod 32 == 8)
#define SSTRIDE   132          // staging row stride

// smem layout (bytes)
#define BPACK_BYTES (NKS * 16 * 32 * 2 * 4)     // 139264
#define BUF_BYTES   (64 * MPAD * 4)             // 34816 per buffer
#define ABUF0_OFF   (BPACK_BYTES)
#define ABUF1_OFF   (ABUF0_OFF + BUF_BYTES)
#define PAR_OFF     (ABUF1_OFF + BUF_BYTES)
#define SMEM_E      (PAR_OFF + 3 * 128 * 4)     // 210432 B

// RBF recurrence: db = (20/15)*0.8 = 16/15; db^2 = 1.13777778
#define DB2   1.13777778f
#define TWODB 2.13333333f

__device__ __forceinline__ uint32_t to_tf32(float f) {
    uint32_t r;
    asm("cvt.rna.tf32.f32 %0, %1;" : "=r"(r) : "f"(f));
    return r;
}

__device__ __forceinline__ void bar_sync(int id) {
    asm volatile("bar.sync %0, %1;" :: "r"(id), "n"(THREADS_E) : "memory");
}
__device__ __forceinline__ void bar_arrive(int id) {
    asm volatile("bar.arrive %0, %1;" :: "r"(id), "n"(THREADS_E) : "memory");
}

__device__ __forceinline__ void mma_tf32(float& d0, float& d1, float& d2, float& d3,
                                         uint32_t a0, uint32_t a1, uint32_t a2, uint32_t a3,
                                         uint32_t b0, uint32_t b1) {
    asm volatile("mma.sync.aligned.m16n8k8.row.col.f32.tf32.tf32.f32 "
                 "{%0,%1,%2,%3},{%4,%5,%6,%7},{%8,%9},{%0,%1,%2,%3};"
                 : "+f"(d0), "+f"(d1), "+f"(d2), "+f"(d3)
                 : "r"(a0), "r"(a1), "r"(a2), "r"(a3), "r"(b0), "r"(b1));
}

__device__ __forceinline__ void norm3g(float& x, float& y, float& z) {
    float n = sqrtf(x*x + y*y + z*z);
    n = (n == 0.0f) ? 1.0f : n;
    float inv = 1.0f / n;
    x *= inv; y *= inv; z *= inv;
}

// compile-time pair index; KB = chunk k-base (rows land in chunk-local buffer)
template<int P, int KB>
__device__ __forceinline__ void rbf_pair(const float* __restrict__ S,
                                         const float* __restrict__ Dv,
                                         uint32_t* __restrict__ buf,
                                         int eP, float k0, float c2)
{
    constexpr int EPa[16] = {1,1,2,1,0,1,3,2,2,0,2,3,0,0,3,3};
    constexpr int EPb[16] = {1,2,1,0,1,3,1,2,0,2,3,2,0,3,0,3};
    const float* sa = S  + EPa[P] * 3;
    const float* db = Dv + EPb[P] * 3;
    float dx = sa[0]-db[0], dy = sa[1]-db[1], dz = sa[2]-db[2];
    float Dd = sqrtf(dx*dx + dy*dy + dz*dz + 1e-6f);
    uint32_t* row = buf + (P * 16 - KB) * MPAD + eP;
    float av = Dd * 0.8f;
    float E0 = __expf(-av * av);
    if (E0 > 0.0f) {
        float rk = __expf(TWODB * av) * k0;
        float v = E0;
        row[0] = to_tf32(v);
        #pragma unroll
        for (int i = 1; i < 16; i++) {
            v *= rk; rk *= c2;
            row[i * MPAD] = to_tf32(v);
        }
    } else {   // D > ~11.7: direct eval (essentially never taken)
        #pragma unroll
        for (int i = 0; i < 16; i++) {
            float t = (Dd - (float)i * (20.0f/15.0f)) * 0.8f;
            row[i * MPAD] = to_tf32(__expf(-t * t));
        }
    }
}

__device__ __forceinline__ void load_afrag(const uint32_t* __restrict__ ap,
                                           uint32_t a[2][4]) {
    #pragma unroll
    for (int i = 0; i < 2; i++) {
        const uint32_t* q = ap + i * 16;
        a[i][0] = q[0];
        a[i][1] = q[8];
        a[i][2] = q[4 * MPAD];
        a[i][3] = q[4 * MPAD + 8];
    }
}
__device__ __forceinline__ void do_mmas(float acc[2][8][4],
                                        const uint32_t a[2][4],
                                        const uint2 b[8]) {
    #pragma unroll
    for (int j = 0; j < 8; j++) {
        mma_tf32(acc[0][j][0], acc[0][j][1], acc[0][j][2], acc[0][j][3],
                 a[0][0], a[0][1], a[0][2], a[0][3], b[j].x, b[j].y);
        mma_tf32(acc[1][j][0], acc[1][j][1], acc[1][j][2], acc[1][j][3],
                 a[1][0], a[1][1], a[1][2], a[1][3], b[j].x, b[j].y);
    }
}

template<int NKSL>
__device__ __forceinline__ void gemm_chunk(float acc[2][8][4],
                                           const uint32_t* __restrict__ Abase,
                                           const uint32_t* __restrict__ Bbase,
                                           int lane, int wm, int wn)
{
    const uint32_t* Ath = Abase + (lane & 3) * MPAD + (lane >> 2) + wm * 32;
    const uint32_t* Bth = Bbase + (wn * 8) * 64 + lane * 2;
    #pragma unroll
    for (int ksl = 0; ksl < NKSL; ksl++) {
        uint32_t a[2][4];
        uint2 b[8];
        load_afrag(Ath + ksl * (8 * MPAD), a);
        #pragma unroll
        for (int j = 0; j < 8; j++)
            b[j] = *(const uint2*)(Bth + ksl * 1024 + j * 64);
        do_mmas(acc, a, b);
    }
}

__global__ void __launch_bounds__(THREADS_E, 1)
edge_kernel_mma(const float* __restrict__ X,
                const int* __restrict__ idxA, const int* __restrict__ idxB,
                const float* __restrict__ Wg, const float* __restrict__ bg,
                const float* __restrict__ gg, const float* __restrict__ betag,
                float* __restrict__ outA, float* __restrict__ outB,
                int E, int N)
{
    constexpr int ORD[4] = {1,0,2,3};

    extern __shared__ char smem[];
    uint32_t* Bp  = (uint32_t*)(smem);
    uint32_t* Ab0 = (uint32_t*)(smem + ABUF0_OFF);
    uint32_t* Ab1 = (uint32_t*)(smem + ABUF1_OFF);
    float*    stg = (float*)(smem + ABUF0_OFF);     // staging overlays both bufs
    float*    sB  = (float*)(smem + PAR_OFF);
    float*    sG  = sB + 128;
    float*    sBe = sG + 128;

    const int tid  = threadIdx.x;
    const int lane = tid & 31;
    const int wid  = tid >> 5;

    const float k0 = __expf(-DB2);
    const float c2 = __expf(-2.0f * DB2);

    // ---- init: pack weights (tf32, fragment-ordered), params ----
    for (int i = tid; i < NKS * 16 * 32; i += THREADS_E) {
        const int l  = i & 31;
        const int nt = (i >> 5) & 15;
        const int ks = i >> 9;
        const int n  = nt * 8 + (l >> 2);
        const int ka = ks * 8 + (l & 3);
        const int kb = ka + 4;
        float w0 = (ka < EK) ? Wg[n * EK + ka] : 0.0f;
        float w1 = (kb < EK) ? Wg[n * EK + kb] : 0.0f;
        Bp[i * 2 + 0] = to_tf32(w0);
        Bp[i * 2 + 1] = to_tf32(w1);
    }
    if (tid < 128) { sB[tid] = bg[tid]; sG[tid] = gg[tid]; sBe[tid] = betag[tid]; }
    __syncthreads();

    const int wm = wid >> 1;          // consumer: m band (wid 0..7)
    const int wn = wid & 1;           // consumer: n band

    const int tilesPer = (E + TILE_E - 1) / TILE_E;
    const int totTiles = 2 * tilesPer;

    for (int tile = blockIdx.x; tile < totTiles; tile += gridDim.x) {
        const int which = (tile >= tilesPer);
        const int* idx  = which ? idxB : idxA;
        float* outp     = which ? outB : outA;
        const int base  = (which ? (tile - tilesPer) : tile) * TILE_E;

        float acc[2][8][4];

        if (wid >= 8) {
            // ================= PRODUCER (4 warps, 1 thread/edge) ============
            const int eP  = tid - 256;
            const int egl = base + eP;
            const int e   = (egl < E) ? egl : (E - 1);
            const int src = idx[e];
            const int dst = idx[E + e];
            const float4* Sp4 = (const float4*)(X + (size_t)src * 12);
            const float4* Dp4 = (const float4*)(X + (size_t)dst * 12);
            float4 s0 = Sp4[0], s1 = Sp4[1], s2 = Sp4[2];
            float4 d0 = Dp4[0], d1 = Dp4[1], d2 = Dp4[2];
            float S[12]  = {s0.x,s0.y,s0.z,s0.w,s1.x,s1.y,s1.z,s1.w,s2.x,s2.y,s2.z,s2.w};
            float Dv[12] = {d0.x,d0.y,d0.z,d0.w,d1.x,d1.y,d1.z,d1.w,d2.x,d2.y,d2.z,d2.w};

            // chunk0 -> buf0 (free at tile start)
            rbf_pair<0,0>(S,Dv,Ab0,eP,k0,c2);
            rbf_pair<1,0>(S,Dv,Ab0,eP,k0,c2);
            rbf_pair<2,0>(S,Dv,Ab0,eP,k0,c2);
            rbf_pair<3,0>(S,Dv,Ab0,eP,k0,c2);
            bar_arrive(1);                       // FULL0
            // chunk1 -> buf1
            rbf_pair<4,64>(S,Dv,Ab1,eP,k0,c2);
            rbf_pair<5,64>(S,Dv,Ab1,eP,k0,c2);
            rbf_pair<6,64>(S,Dv,Ab1,eP,k0,c2);
            rbf_pair<7,64>(S,Dv,Ab1,eP,k0,c2);
            bar_arrive(2);                       // FULL1
            // chunk2 -> buf0
            bar_sync(3);                         // FREE0
            rbf_pair<8,128>(S,Dv,Ab0,eP,k0,c2);
            rbf_pair<9,128>(S,Dv,Ab0,eP,k0,c2);
            rbf_pair<10,128>(S,Dv,Ab0,eP,k0,c2);
            rbf_pair<11,128>(S,Dv,Ab0,eP,k0,c2);
            bar_arrive(1);                       // FULL0
            // chunk3 -> buf1
            bar_sync(4);                         // FREE1
            rbf_pair<12,192>(S,Dv,Ab1,eP,k0,c2);
            rbf_pair<13,192>(S,Dv,Ab1,eP,k0,c2);
            rbf_pair<14,192>(S,Dv,Ab1,eP,k0,c2);
            rbf_pair<15,192>(S,Dv,Ab1,eP,k0,c2);
            bar_arrive(2);                       // FULL1
            // chunk4 (dirs, k 256..271) -> buf0 rows 0..15
            bar_sync(3);                         // FREE0
            {
                float q0x=0.f,q0y=0.f,q0z=0.f,q1x=0.f,q1y=0.f,q1z=0.f,
                      q2x=0.f,q2y=0.f,q2z=0.f;
                if (src != N - 1) {
                    float u0x=S[3]-S[0], u0y=S[4]-S[1], u0z=S[5]-S[2];
                    norm3g(u0x,u0y,u0z);
                    float u1x=S[6]-S[3], u1y=S[7]-S[4], u1z=S[8]-S[5];
                    norm3g(u1x,u1y,u1z);
                    float nx=u0y*u1z-u0z*u1y, ny=u0z*u1x-u0x*u1z, nz=u0x*u1y-u0y*u1x;
                    norm3g(nx,ny,nz);
                    float bx=u0x-u1x, by=u0y-u1y, bz=u0z-u1z;
                    norm3g(bx,by,bz);
                    float cx=by*nz-bz*ny, cy=bz*nx-bx*nz, cz=bx*ny-by*nx;
                    q0x=bx;q0y=by;q0z=bz; q1x=nx;q1y=ny;q1z=nz; q2x=cx;q2y=cy;q2z=cz;
                }
                uint32_t* dbase = Ab0 + eP;
                #pragma unroll
                for (int a = 0; a < 4; a++) {
                    const float* da = Dv + ORD[a] * 3;
                    float xx=da[0]-S[0], xy=da[1]-S[1], xz=da[2]-S[2];
                    float vx=q0x*xx+q1x*xy+q2x*xz;
                    float vy=q0y*xx+q1y*xy+q2y*xz;
                    float vz=q0z*xx+q1z*xy+q2z*xz;
                    norm3g(vx,vy,vz);
                    dbase[(a*3+0)*MPAD] = to_tf32(vx);
                    dbase[(a*3+1)*MPAD] = to_tf32(vy);
                    dbase[(a*3+2)*MPAD] = to_tf32(vz);
                }
                dbase[12*MPAD] = 0u;
                dbase[13*MPAD] = 0u;
                dbase[14*MPAD] = 0u;
                dbase[15*MPAD] = 0u;
            }
            bar_arrive(1);                       // FULL0
        } else {
            // ================= CONSUMER (8 warps, 128x128 GEMM) =============
            #pragma unroll
            for (int i = 0; i < 2; i++)
                #pragma unroll
                for (int j = 0; j < 8; j++)
                    #pragma unroll
                    for (int c = 0; c < 4; c++) acc[i][j][c] = 0.0f;

            bar_sync(1);                                   // FULL0
            gemm_chunk<8>(acc, Ab0, Bp + 0 * 1024, lane, wm, wn);
            bar_arrive(3);                                 // FREE0
            bar_sync(2);                                   // FULL1
            gemm_chunk<8>(acc, Ab1, Bp + 8 * 1024, lane, wm, wn);
            bar_arrive(4);                                 // FREE1
            bar_sync(1);                                   // FULL0
            gemm_chunk<8>(acc, Ab0, Bp + 16 * 1024, lane, wm, wn);
            bar_arrive(3);                                 // FREE0
            bar_sync(2);                                   // FULL1
            gemm_chunk<8>(acc, Ab1, Bp + 24 * 1024, lane, wm, wn);
            bar_sync(1);                                   // FULL0
            gemm_chunk<2>(acc, Ab0, Bp + 32 * 1024, lane, wm, wn);
        }
        __syncthreads();   // all chunks consumed; buffers become staging

        // ================= epilogue (consumers hold accs) ==================
        if (tid < 256) {
            #pragma unroll
            for (int i = 0; i < 2; i++) {
                const int m = wm * 32 + i * 16 + (lane >> 2);
                #pragma unroll
                for (int j = 0; j < 8; j++) {
                    const int n = wn * 64 + j * 8 + (lane & 3) * 2;
                    *(float2*)(stg + m * SSTRIDE + n)       =
                        make_float2(acc[i][j][0], acc[i][j][1]);
                    *(float2*)(stg + (m + 8) * SSTRIDE + n) =
                        make_float2(acc[i][j][2], acc[i][j][3]);
                }
            }
        }
        __syncthreads();

        if (tid < 256) {
            const int er   = tid >> 1;
            const int half = tid & 1;
            float* row = stg + er * SSTRIDE + half * 64;
            float v[64];
            float sum = 0.0f;
            #pragma unroll
            for (int c = 0; c < 64; c += 4) {
                float4 x = *(const float4*)(row + c);
                v[c+0] = x.x + sB[half*64 + c+0];
                v[c+1] = x.y + sB[half*64 + c+1];
                v[c+2] = x.z + sB[half*64 + c+2];
                v[c+3] = x.w + sB[half*64 + c+3];
                sum += v[c+0] + v[c+1] + v[c+2] + v[c+3];
            }
            sum += __shfl_xor_sync(0xffffffffu, sum, 1);
            float mu = sum * (1.0f / 128.0f);
            float sq = 0.0f;
            #pragma unroll
            for (int c = 0; c < 64; c++) {
                float d = v[c] - mu;
                v[c] = d;
                sq += d * d;
            }
            sq += __shfl_xor_sync(0xffffffffu, sq, 1);
            float inv = 1.0f / (sqrtf(sq * (1.0f / 127.0f) + 1e-6f) + 1e-6f);
            #pragma unroll
            for (int c = 0; c < 64; c += 4) {
                float4 o;
                o.x = sG[half*64 + c+0] * v[c+0] * inv + sBe[half*64 + c+0];
                o.y = sG[half*64 + c+1] * v[c+1] * inv + sBe[half*64 + c+1];
                o.z = sG[half*64 + c+2] * v[c+2] * inv + sBe[half*64 + c+2];
                o.w = sG[half*64 + c+3] * v[c+3] * inv + sBe[half*64 + c+3];
                *(float4*)(row + c) = o;
            }
        }
        __syncthreads();

        if (tid < 256) {
            const int c0 = (tid & 31) * 4;
            const int r0 = tid >> 5;
            #pragma unroll
            for (int i = 0; i < 16; i++) {
                const int r = r0 + i * 8;
                const int eo = base + r;
                if (eo < E) {
                    float4 x = *(const float4*)(stg + r * SSTRIDE + c0);
                    *(float4*)(outp + (size_t)eo * DC + c0) = x;
                }
            }
        }
        __syncthreads();   // staging/bufs free before next tile's producer
    }
}

// ===================== node kernel (fp32 f32x2) ============================
#define THREADS_N 256
#define TILE_N 64
#define FSN 68
#define NK 96

__device__ __forceinline__ unsigned long long pack2(float a) {
    unsigned long long r;
    unsigned int ai = __float_as_uint(a);
    asm("mov.b64 %0, {%1, %1};" : "=l"(r) : "r"(ai));
    return r;
}
__device__ __forceinline__ void fma2(unsigned long long& d,
                                     unsigned long long a,
                                     unsigned long long b) {
    asm("fma.rn.f32x2 %0, %1, %2, %0;" : "+l"(d) : "l"(a), "l"(b));
}

__global__ void __launch_bounds__(THREADS_N, 1)
node_kernel(const float* __restrict__ X,
            const float* __restrict__ Wg, const float* __restrict__ bg,
            const float* __restrict__ gg, const float* __restrict__ betag,
            float* __restrict__ out, int N)
{
    constexpr int NPa[6] = {1,1,1,0,0,3};
    constexpr int NPb[6] = {0,2,3,2,3,2};
    extern __shared__ float sm[];
    float* Wsm = sm;
    float* F   = Wsm + NK * DC;
    float* sB  = F + NK * FSN;
    float* sG  = sB + DC;
    float* sBe = sG + DC;

    const int tid = threadIdx.x;
    const float k0 = __expf(-DB2);
    const float c2 = __expf(-2.0f * DB2);

    for (int i = tid; i < NK * DC; i += THREADS_N) {
        int k = i >> 7, c = i & 127;
        Wsm[i] = Wg[c * NK + k];
    }
    if (tid < DC) { sB[tid] = bg[tid]; sG[tid] = gg[tid]; sBe[tid] = betag[tid]; }
    __syncthreads();

    const int j    = tid & 3;
    const int eloc = tid >> 2;
    const int cidx = tid & 31;
    const int eg   = tid >> 5;
    const int eBase = eg * 8;
    const int c0   = cidx * 4;
    const int base = blockIdx.x * TILE_N;

    {
        const int n = base + eloc;
        if (n < N) {
            const float* Sx = X + (size_t)n * 12;
            #pragma unroll
            for (int pp = 0; pp < 2; pp++) {
                const int p = j + pp * 4;
                if (p < 6) {
                    const float* sa = Sx + NPa[p] * 3;
                    const float* sb = Sx + NPb[p] * 3;
                    float dx = sa[0]-sb[0], dy = sa[1]-sb[1], dz = sa[2]-sb[2];
                    float Dd = sqrtf(dx*dx + dy*dy + dz*dz + 1e-6f);
                    float* frow = F + (p * 16) * FSN + eloc;
                    float av = Dd * 0.8f;
                    float E0 = __expf(-av * av);
                    if (E0 > 0.0f) {
                        float rk = __expf(TWODB * av) * k0;
                        float v = E0;
                        frow[0] = v;
                        #pragma unroll
                        for (int i = 1; i < 16; i++) {
                            v *= rk; rk *= c2;
                            frow[i * FSN] = v;
                        }
                    } else {
                        #pragma unroll
                        for (int i = 0; i < 16; i++) {
                            float t = (Dd - (float)i * (20.0f/15.0f)) * 0.8f;
                            frow[i * FSN] = __expf(-t * t);
                        }
                    }
                }
            }
        }
    }
    __syncthreads();

    unsigned long long acc[4][4];
    #pragma unroll
    for (int q = 0; q < 4; q++)
        #pragma unroll
        for (int cc = 0; cc < 4; cc++) acc[q][cc] = 0ull;

    #pragma unroll 4
    for (int k = 0; k < NK; k++) {
        const ulonglong2* fp = (const ulonglong2*)(F + k * FSN + eBase);
        ulonglong2 fa = fp[0];
        ulonglong2 fb = fp[1];
        const float4 w = *(const float4*)(Wsm + k * DC + c0);
        unsigned long long w0 = pack2(w.x), w1 = pack2(w.y);
        unsigned long long w2 = pack2(w.z), w3 = pack2(w.w);
        unsigned long long f2[4] = {fa.x, fa.y, fb.x, fb.y};
        #pragma unroll
        for (int q = 0; q < 4; q++) {
            fma2(acc[q][0], f2[q], w0);
            fma2(acc[q][1], f2[q], w1);
            fma2(acc[q][2], f2[q], w2);
            fma2(acc[q][3], f2[q], w3);
        }
    }

    float v[8][4];
    #pragma unroll
    for (int q = 0; q < 4; q++)
        #pragma unroll
        for (int cc = 0; cc < 4; cc++) {
            union { unsigned long long u; float2 f; } cv;
            cv.u = acc[q][cc];
            v[2*q][cc]   = cv.f.x;
            v[2*q+1][cc] = cv.f.y;
        }
    const float b0=sB[c0], b1=sB[c0+1], b2=sB[c0+2], b3=sB[c0+3];
    const float g0=sG[c0], g1=sG[c0+1], g2=sG[c0+2], g3=sG[c0+3];
    const float t0=sBe[c0],t1=sBe[c0+1],t2=sBe[c0+2],t3=sBe[c0+3];

    #pragma unroll
    for (int s = 0; s < 8; s++) {
        float x0=v[s][0]+b0, x1=v[s][1]+b1, x2=v[s][2]+b2, x3=v[s][3]+b3;
        float sum = x0+x1+x2+x3;
        #pragma unroll
        for (int m = 16; m > 0; m >>= 1) sum += __shfl_xor_sync(0xffffffffu, sum, m);
        float mu = sum * (1.0f/128.0f);
        float d0=x0-mu, d1=x1-mu, d2=x2-mu, d3=x3-mu;
        float sq = d0*d0+d1*d1+d2*d2+d3*d3;
        #pragma unroll
        for (int m = 16; m > 0; m >>= 1) sq += __shfl_xor_sync(0xffffffffu, sq, m);
        float inv = 1.0f / (sqrtf(sq * (1.0f/127.0f) + 1e-6f) + 1e-6f);
        const int n2 = base + eBase + s;
        if (n2 < N) {
            float4 o;
            o.x = g0*d0*inv + t0;
            o.y = g1*d1*inv + t1;
            o.z = g2*d2*inv + t2;
            o.w = g3*d3*inv + t3;
            *(float4*)(out + (size_t)n2 * DC + c0) = o;
        }
    }
}

// ===================== launch =====================
extern "C" void kernel_launch(void* const* d_in, const int* in_sizes, int n_in,
                              void* d_out, int out_size)
{
    const float* X   = (const float*)d_in[0];
    const int*   Ein = (const int*)d_in[1];
    const int*   Eex = (const int*)d_in[2];
    const float* nW  = (const float*)d_in[3];
    const float* nb  = (const float*)d_in[4];
    const float* eW  = (const float*)d_in[5];
    const float* eb  = (const float*)d_in[6];
    const float* gn  = (const float*)d_in[7];
    const float* bn  = (const float*)d_in[8];
    const float* ge  = (const float*)d_in[9];
    const float* be  = (const float*)d_in[10];

    const int N = in_sizes[0] / 12;
    const int E = in_sizes[1] / 2;

    float* out   = (float*)d_out;
    float* outV  = out;
    float* outIn = out + (size_t)N * DC;
    float* outEx = outIn + (size_t)E * DC;

    const size_t smN = (size_t)(NK * DC + NK * FSN + 3 * DC) * sizeof(float);
    cudaFuncSetAttribute(edge_kernel_mma,
                         cudaFuncAttributeMaxDynamicSharedMemorySize, SMEM_E);
    cudaFuncSetAttribute(node_kernel,
                         cudaFuncAttributeMaxDynamicSharedMemorySize, (int)smN);

    int sms = 148;
    cudaDeviceGetAttribute(&sms, cudaDevAttrMultiProcessorCount, 0);

    const int nTiles = (N + TILE_N - 1) / TILE_N;
    node_kernel<<<nTiles, THREADS_N, smN>>>(X, nW, nb, gn, bn, outV, N);
    edge_kernel_mma<<<sms, THREADS_E, SMEM_E>>>(X, Ein, Eex, eW, eb, ge, be,
                                                outIn, outEx, E, N);
}